// round 1
// baseline (speedup 1.0000x reference)
#include <cuda_runtime.h>
#include <cuda_bf16.h>

// LSTM_WP: B=4096 independent LSTM chains, T=128, H=128, input_size=1.
// gates[b,g] = x[b,t]*W_ih[g] + b_ih[g] + b_hh[g] + sum_k W_hh[g,k]*h[b,k]
// i,f,g,o = rows [0:128),[128:256),[256:384),[384:512)
// c = sig(f)*c + sig(i)*tanh(g);  h = sig(o)*tanh(c)
// out[b] = dot(h_T[b], fc_W) + fc_b
//
// Design: persistent per batch-tile. 256 CTAs x 256 threads, BTILE=16.
// Thread (bg,jg): bg = tid>>6 (4 batch groups of 4), jg = tid&63 (2 hidden
// units j0=2*jg, j0+1, all 4 gates). 32 fp32 accumulators/thread, c-state in
// registers, h in smem (warp-broadcast reads). W_hh streamed from L2 via
// float4 LDG (L2-resident 256KB shared by all CTAs).

#define HH 128
#define TT 128
#define BTILE 16
#define NTHREADS 256

__device__ __forceinline__ float fsigmoid(float x) {
    x = fmaxf(-30.0f, fminf(30.0f, x));
    float e = __expf(-x);
    return __fdividef(1.0f, 1.0f + e);
}

__device__ __forceinline__ float ftanh_fast(float x) {
    x = fmaxf(-15.0f, fminf(15.0f, x));
    float e = __expf(2.0f * x);
    return __fdividef(e - 1.0f, e + 1.0f);
}

__global__ __launch_bounds__(NTHREADS, 2)
void lstm_wp_kernel(const float* __restrict__ x,
                    const float* __restrict__ W_ih,
                    const float* __restrict__ W_hh,
                    const float* __restrict__ b_ih,
                    const float* __restrict__ b_hh,
                    const float* __restrict__ fc_W,
                    const float* __restrict__ fc_b,
                    float* __restrict__ out)
{
    __shared__ float h_s[BTILE][HH];
    __shared__ float x_s[BTILE][TT];

    const int tid    = threadIdx.x;
    const int bg     = tid >> 6;      // 0..3   (batch group)
    const int jg     = tid & 63;      // 0..63  (hidden-unit pair)
    const int j0     = jg * 2;
    const int b_base = bg * 4;
    const int cta_b0 = blockIdx.x * BTILE;

    // --- load x tile for this CTA's 16 batches (coalesced float4) ---
    {
        const float4* xg = (const float4*)(x + (size_t)cta_b0 * TT);
        float4* xs = (float4*)&x_s[0][0];
        #pragma unroll
        for (int i = tid; i < BTILE * TT / 4; i += NTHREADS) xs[i] = xg[i];
    }
    // --- zero h ---
    #pragma unroll
    for (int i = tid; i < BTILE * HH; i += NTHREADS) ((float*)h_s)[i] = 0.0f;

    // --- per-thread gate-row constants: rows r = g*128 + j0 + jj, idx = g*2+jj ---
    float wi[8], bs[8];
    #pragma unroll
    for (int g = 0; g < 4; g++) {
        #pragma unroll
        for (int jj = 0; jj < 2; jj++) {
            int row = g * HH + j0 + jj;
            wi[g * 2 + jj] = W_ih[row];
            bs[g * 2 + jj] = b_ih[row] + b_hh[row];
        }
    }

    // --- W_hh row-pair base pointers (float4 granularity). Row r occupies
    //     32 float4s; second row of the pair is at compile-time offset +32. ---
    const float4* wp[4];
    #pragma unroll
    for (int g = 0; g < 4; g++)
        wp[g] = (const float4*)W_hh + (size_t)(g * HH + j0) * (HH / 4);

    float c[4][2];
    #pragma unroll
    for (int b = 0; b < 4; b++) { c[b][0] = 0.0f; c[b][1] = 0.0f; }

    __syncthreads();

    for (int t = 0; t < TT; t++) {
        float acc[4][8];
        #pragma unroll
        for (int b = 0; b < 4; b++)
            #pragma unroll
            for (int r = 0; r < 8; r++) acc[b][r] = 0.0f;

        // --- GEMM: acc[b][g*2+jj] += sum_k W_hh[g*128+j0+jj][k] * h[b][k] ---
        #pragma unroll 2
        for (int kq = 0; kq < HH / 4; kq++) {
            float4 h4[4];
            #pragma unroll
            for (int b = 0; b < 4; b++)
                h4[b] = *(const float4*)(&h_s[b_base + b][kq << 2]);
            #pragma unroll
            for (int g = 0; g < 4; g++) {
                const float4 w0 = wp[g][kq];            // row j0
                const float4 w1 = wp[g][kq + HH / 4];   // row j0+1
                #pragma unroll
                for (int b = 0; b < 4; b++) {
                    float a0 = acc[b][g * 2 + 0];
                    float a1 = acc[b][g * 2 + 1];
                    a0 = fmaf(w0.x, h4[b].x, a0);
                    a0 = fmaf(w0.y, h4[b].y, a0);
                    a0 = fmaf(w0.z, h4[b].z, a0);
                    a0 = fmaf(w0.w, h4[b].w, a0);
                    a1 = fmaf(w1.x, h4[b].x, a1);
                    a1 = fmaf(w1.y, h4[b].y, a1);
                    a1 = fmaf(w1.z, h4[b].z, a1);
                    a1 = fmaf(w1.w, h4[b].w, a1);
                    acc[b][g * 2 + 0] = a0;
                    acc[b][g * 2 + 1] = a1;
                }
            }
        }

        __syncthreads();  // all h_s reads done before overwrite

        // --- gate nonlinearities + state update ---
        #pragma unroll
        for (int b = 0; b < 4; b++) {
            const float xt = x_s[b_base + b][t];
            #pragma unroll
            for (int jj = 0; jj < 2; jj++) {
                float gi = fsigmoid (fmaf(xt, wi[0 + jj], bs[0 + jj]) + acc[b][0 + jj]);
                float gf = fsigmoid (fmaf(xt, wi[2 + jj], bs[2 + jj]) + acc[b][2 + jj]);
                float gg = ftanh_fast(fmaf(xt, wi[4 + jj], bs[4 + jj]) + acc[b][4 + jj]);
                float go = fsigmoid (fmaf(xt, wi[6 + jj], bs[6 + jj]) + acc[b][6 + jj]);
                float cn = fmaf(gf, c[b][jj], gi * gg);
                c[b][jj] = cn;
                h_s[b_base + b][j0 + jj] = go * ftanh_fast(cn);
            }
        }

        __syncthreads();  // new h visible before next step's reads
    }

    // --- fc head: out[b] = dot(h_T[b], fc_W) + fc_b[0] ---
    const int wid  = tid >> 5;
    const int lane = tid & 31;
    #pragma unroll
    for (int bb = 0; bb < 2; bb++) {
        const int b = wid * 2 + bb;
        float s = 0.0f;
        #pragma unroll
        for (int k = lane; k < HH; k += 32)
            s = fmaf(h_s[b][k], fc_W[k], s);
        #pragma unroll
        for (int off = 16; off; off >>= 1)
            s += __shfl_xor_sync(0xffffffffu, s, off);
        if (lane == 0) out[cta_b0 + b] = s + fc_b[0];
    }
}

extern "C" void kernel_launch(void* const* d_in, const int* in_sizes, int n_in,
                              void* d_out, int out_size)
{
    const float* x    = (const float*)d_in[0];
    const float* W_ih = (const float*)d_in[1];
    const float* W_hh = (const float*)d_in[2];
    const float* b_ih = (const float*)d_in[3];
    const float* b_hh = (const float*)d_in[4];
    const float* fc_W = (const float*)d_in[5];
    const float* fc_b = (const float*)d_in[6];

    const int B = in_sizes[0] / TT;        // 4096
    const int grid = B / BTILE;            // 256

    lstm_wp_kernel<<<grid, NTHREADS>>>(x, W_ih, W_hh, b_ih, b_hh,
                                       fc_W, fc_b, (float*)d_out);
}

// round 2
// speedup vs baseline: 5.0204x; 5.0204x over previous
#include <cuda_runtime.h>
#include <cuda_bf16.h>

// LSTM_WP: B=4096 chains, T=128, H=128, input_size=1.
// Round 2: coalesced column-major weights + f32x2 packed FMA.
//
// Thread j (0..127) owns hidden unit j: rows {g*128+j} for g=i,f,g,o, for all
// 16 batches of its CTA. Weights pre-transposed into W_re2[kp][row][2] so a
// warp's LDG.64 covers 32 consecutive 8B chunks (2 lines vs 32 before).
// k-pairs packed into f32x2 lanes; horizontal add once per timestep.
// h double-buffered in smem -> 1 syncthreads per step.

#define HH 128
#define TT 128
#define BTILE 16
#define NTHREADS 128
#define NKP 64

typedef unsigned long long ull;

__device__ __align__(16) float W_re2[4 * HH * HH];   // 512*128 floats, [kp][row][2]

__global__ void prep_w(const float* __restrict__ W_hh) {
    int idx = blockIdx.x * blockDim.x + threadIdx.x;   // 0..65535, src-linear
    int row = idx >> 7;          // 0..511
    int k   = idx & 127;
    W_re2[(k >> 1) * 1024 + row * 2 + (k & 1)] = W_hh[idx];
}

#define FMA2(acc, a, b) \
    asm("fma.rn.f32x2 %0, %1, %2, %3;" : "=l"(acc) : "l"(a), "l"(b), "l"(acc))

__device__ __forceinline__ float tanh_ap(float x) {
    float y;
    asm("tanh.approx.f32 %0, %1;" : "=f"(y) : "f"(x));
    return y;
}
__device__ __forceinline__ float sig_ap(float x) {
    return fmaf(tanh_ap(0.5f * x), 0.5f, 0.5f);
}

__global__ __launch_bounds__(NTHREADS, 2)
void lstm_wp_kernel(const float* __restrict__ x,
                    const float* __restrict__ W_ih,
                    const float* __restrict__ b_ih,
                    const float* __restrict__ b_hh,
                    const float* __restrict__ fc_W,
                    const float* __restrict__ fc_b,
                    float* __restrict__ out)
{
    __shared__ float h_s[2][BTILE][HH];   // double-buffered hidden state
    __shared__ float x_s[BTILE][TT];

    const int tid    = threadIdx.x;
    const int j      = tid;               // hidden unit owned by this thread
    const int cta_b0 = blockIdx.x * BTILE;

    // coalesced x tile load
    {
        const float4* xg = (const float4*)(x + (size_t)cta_b0 * TT);
        float4* xs = (float4*)&x_s[0][0];
        #pragma unroll
        for (int i = tid; i < BTILE * TT / 4; i += NTHREADS) xs[i] = xg[i];
    }
    // zero initial h
    #pragma unroll
    for (int i = tid; i < BTILE * HH; i += NTHREADS)
        ((float*)h_s[0])[i] = 0.0f;

    // per-thread gate constants
    float wi[4], bs[4];
    #pragma unroll
    for (int g = 0; g < 4; g++) {
        int row = g * HH + j;
        wi[g] = W_ih[row];
        bs[g] = b_ih[row] + b_hh[row];
    }

    float c[BTILE];
    #pragma unroll
    for (int b = 0; b < BTILE; b++) c[b] = 0.0f;

    const ull* __restrict__ Wp = (const ull*)W_re2;   // element = (kp*512 + row)

    __syncthreads();

    int cur = 0;
    for (int t = 0; t < TT; t++) {
        ull acc[4][BTILE];
        #pragma unroll
        for (int g = 0; g < 4; g++)
            #pragma unroll
            for (int b = 0; b < BTILE; b++) acc[g][b] = 0ull;

        const float* hrow = &h_s[cur][0][0];

        #pragma unroll 8
        for (int kp = 0; kp < NKP; kp++) {
            ull w2[4];
            #pragma unroll
            for (int g = 0; g < 4; g++)
                w2[g] = Wp[kp * 512 + g * HH + j];          // LDG.64, coalesced
            #pragma unroll
            for (int b = 0; b < BTILE; b++) {
                ull h2 = *(const ull*)(hrow + b * HH + 2 * kp);  // LDS.64 broadcast
                FMA2(acc[0][b], w2[0], h2);
                FMA2(acc[1][b], w2[1], h2);
                FMA2(acc[2][b], w2[2], h2);
                FMA2(acc[3][b], w2[3], h2);
            }
        }

        // epilogue: horizontal add + activations + state update
        float* hnew = &h_s[cur ^ 1][0][0];
        #pragma unroll
        for (int b = 0; b < BTILE; b++) {
            const float xt = x_s[b][t];
            float pre[4];
            #pragma unroll
            for (int g = 0; g < 4; g++) {
                unsigned lo, hi;
                asm("mov.b64 {%0, %1}, %2;" : "=r"(lo), "=r"(hi) : "l"(acc[g][b]));
                pre[g] = fmaf(xt, wi[g], bs[g]) +
                         (__uint_as_float(lo) + __uint_as_float(hi));
            }
            float gi = sig_ap(pre[0]);
            float gf = sig_ap(pre[1]);
            float gg = tanh_ap(pre[2]);
            float go = sig_ap(pre[3]);
            float cn = fmaf(gf, c[b], gi * gg);
            c[b] = cn;
            hnew[b * HH + j] = go * tanh_ap(cn);
        }
        __syncthreads();
        cur ^= 1;
    }

    // fc head: out[b] = dot(h_final[b], fc_W) + fc_b[0]
    const int wid  = tid >> 5;
    const int lane = tid & 31;
    #pragma unroll
    for (int bb = 0; bb < 4; bb++) {
        const int b = wid * 4 + bb;
        float s = 0.0f;
        #pragma unroll
        for (int q = 0; q < 4; q++) {
            int k = lane + q * 32;
            s = fmaf(h_s[cur][b][k], fc_W[k], s);
        }
        #pragma unroll
        for (int off = 16; off; off >>= 1)
            s += __shfl_xor_sync(0xffffffffu, s, off);
        if (lane == 0) out[cta_b0 + b] = s + fc_b[0];
    }
}

extern "C" void kernel_launch(void* const* d_in, const int* in_sizes, int n_in,
                              void* d_out, int out_size)
{
    const float* x    = (const float*)d_in[0];
    const float* W_ih = (const float*)d_in[1];
    const float* W_hh = (const float*)d_in[2];
    const float* b_ih = (const float*)d_in[3];
    const float* b_hh = (const float*)d_in[4];
    const float* fc_W = (const float*)d_in[5];
    const float* fc_b = (const float*)d_in[6];

    const int B = in_sizes[0] / TT;        // 4096
    const int grid = B / BTILE;            // 256

    prep_w<<<256, 256>>>(W_hh);
    lstm_wp_kernel<<<grid, NTHREADS>>>(x, W_ih, b_ih, b_hh,
                                       fc_W, fc_b, (float*)d_out);
}

// round 4
// speedup vs baseline: 16.2635x; 3.2395x over previous
#include <cuda_runtime.h>
#include <cuda_bf16.h>
#include <cstdint>

// LSTM_WP via mma.sync tf32 (non-'a' PTX; runs as HMMA on sm_103a).
// Cluster of 2 CTAs; CTA rank c owns gate-rows for units c*64..c*64+63 (all
// 4 gates, M=256), W held in REGISTERS (128 tf32 frags/thread, loaded once).
// Per step: D[256,64] = W_c[256,128] @ h[128,64] via m16n8k8 tf32 MMAs; h in
// smem pair-packed [kt][n][tig][2] so B-frags are conflict-free LDS.64.
// Epilogue computes gates in-thread (each thread owns one unit x 16 batches),
// writes tf32-rounded h to local + peer smem (st.shared::cluster).
// Sync: two cluster mbarriers (hready/rdone, 16 arrivals) per step.

#define TT 128
#define NTHR 256
#define OFF_H   0                      // 32 KB pair-packed h
#define OFF_X   32768                  // 64 x 129 x 4 = 33024 B padded x
#define OFF_BAR (32768 + 33024)        // 65792
#define SMEM_REQ (OFF_BAR + 32)

__device__ __forceinline__ uint32_t smem_u32(const void* p) {
    uint32_t a;
    asm("{ .reg .u64 t; cvta.to.shared.u64 t, %1; cvt.u32.u64 %0, t; }" : "=r"(a) : "l"(p));
    return a;
}
__device__ __forceinline__ uint32_t ctarank() {
    uint32_t r; asm("mov.u32 %0, %%cluster_ctarank;" : "=r"(r)); return r;
}
__device__ __forceinline__ uint32_t rna_tf32(float x) {
    uint32_t r; asm("cvt.rna.tf32.f32 %0, %1;" : "=r"(r) : "f"(x)); return r;
}
__device__ __forceinline__ float tanh_ap(float x) {
    float y; asm("tanh.approx.f32 %0, %1;" : "=f"(y) : "f"(x)); return y;
}
__device__ __forceinline__ float sig_ap(float x) { return fmaf(tanh_ap(0.5f * x), 0.5f, 0.5f); }

#define MBAR_INIT(a, n) \
    asm volatile("mbarrier.init.shared.b64 [%0], %1;" :: "r"(a), "r"((uint32_t)(n)) : "memory")

#define ARRIVE_BOTH(addr, peer) do { \
    asm volatile("mbarrier.arrive.release.cluster.shared::cta.b64 _, [%0];" \
                 :: "r"(addr) : "memory"); \
    asm volatile("{ .reg .b32 ra; mapa.shared::cluster.u32 ra, %0, %1;" \
                 " mbarrier.arrive.release.cluster.shared::cluster.b64 _, [ra]; }" \
                 :: "r"(addr), "r"((uint32_t)(peer)) : "memory"); \
} while (0)

__device__ __forceinline__ void mbar_wait(uint32_t a, uint32_t par) {
    uint32_t done;
    do {
        asm volatile("{ .reg .pred p;"
                     " mbarrier.try_wait.parity.acquire.cluster.shared::cta.b64 p, [%1], %2, 0x989680;"
                     " selp.b32 %0,1,0,p; }"
                     : "=r"(done) : "r"(a), "r"(par) : "memory");
    } while (!done);
}

#define CLUSTER_SYNC() do { \
    asm volatile("barrier.cluster.arrive.aligned;" ::: "memory"); \
    asm volatile("barrier.cluster.wait.aligned;"   ::: "memory"); } while (0)

#define MMA_TF32(d, a, b0, b1) \
    asm volatile("mma.sync.aligned.m16n8k8.row.col.f32.tf32.tf32.f32 " \
                 "{%0,%1,%2,%3}, {%4,%5,%6,%7}, {%8,%9}, {%0,%1,%2,%3};" \
                 : "+f"((d)[0]), "+f"((d)[1]), "+f"((d)[2]), "+f"((d)[3]) \
                 : "r"((a)[0]), "r"((a)[1]), "r"((a)[2]), "r"((a)[3]), \
                   "r"(b0), "r"(b1))

__global__ __launch_bounds__(NTHR, 1) __cluster_dims__(2, 1, 1)
void lstm_mma(const float* __restrict__ x,
              const float* __restrict__ W_ih,
              const float* __restrict__ W_hh,
              const float* __restrict__ b_ih,
              const float* __restrict__ b_hh,
              const float* __restrict__ fc_W,
              const float* __restrict__ fc_b,
              float* __restrict__ out)
{
    extern __shared__ char sm[];
    const uint32_t sbase = smem_u32(sm);
    const int tid  = threadIdx.x;
    const int wid  = tid >> 5, lane = tid & 31;
    const int gid  = lane >> 2, tig = lane & 3;
    const uint32_t crank = ctarank();
    const uint32_t peer  = crank ^ 1u;
    const int clid = blockIdx.x >> 1;

    const uint32_t hready = sbase + OFF_BAR;
    const uint32_t rdone  = sbase + OFF_BAR + 8;

    if (tid == 0) { MBAR_INIT(hready, 16); MBAR_INIT(rdone, 16); }

    // zero h buffer (32KB), load x tile into padded x_s[64][129]
    {
        float4 z = make_float4(0.f, 0.f, 0.f, 0.f);
        float4* hz = (float4*)(sm + OFF_H);
        #pragma unroll
        for (int i = tid; i < 2048; i += NTHR) hz[i] = z;
        const float4* xg = (const float4*)(x + (size_t)clid * 64 * TT);
        float* xs = (float*)(sm + OFF_X);
        #pragma unroll
        for (int i = tid; i < 2048; i += NTHR) {
            float4 v = xg[i];
            int n = i >> 5, q = (i & 31) * 4;
            float* d = xs + n * 129 + q;
            d[0] = v.x; d[1] = v.y; d[2] = v.z; d[3] = v.w;
        }
    }
    __syncthreads();
    CLUSTER_SYNC();   // peer mbars + smem ready

    // ---- W fragments in registers (tf32-rounded) ----
    const int u = (int)crank * 64 + wid * 8 + gid;   // hidden unit 0..127
    uint32_t wreg[2][16][4];
    #pragma unroll
    for (int mt = 0; mt < 2; mt++) {
        const float* rl = W_hh + (size_t)((2 * mt)     * 128 + u) * 128;
        const float* rh = W_hh + (size_t)((2 * mt + 1) * 128 + u) * 128;
        #pragma unroll
        for (int kt = 0; kt < 16; kt++) {
            int k0 = kt * 8 + tig;
            wreg[mt][kt][0] = rna_tf32(__ldg(rl + k0));
            wreg[mt][kt][1] = rna_tf32(__ldg(rh + k0));
            wreg[mt][kt][2] = rna_tf32(__ldg(rl + k0 + 4));
            wreg[mt][kt][3] = rna_tf32(__ldg(rh + k0 + 4));
        }
    }
    float wi[4], bsv[4];
    #pragma unroll
    for (int g = 0; g < 4; g++) {
        int row = g * 128 + u;
        wi[g] = W_ih[row]; bsv[g] = b_ih[row] + b_hh[row];
    }

    uint32_t hRbase;   // peer h buffer base
    asm("mapa.shared::cluster.u32 %0, %1, %2;" : "=r"(hRbase) : "r"(sbase + OFF_H), "r"(peer));

    const uint32_t hb_lane = sbase + OFF_H + gid * 32 + tig * 8;      // B-frag base
    const uint32_t hwL = sbase + OFF_H + ((u >> 3) * 2048 + (u & 3) * 8 + ((u >> 2) & 1) * 4);
    const uint32_t hwR = hRbase         + ((u >> 3) * 2048 + (u & 3) * 8 + ((u >> 2) & 1) * 4);
    const float* xs = (const float*)(sm + OFF_X);

    float cst[16];
    #pragma unroll
    for (int i = 0; i < 16; i++) cst[i] = 0.f;

    if (lane == 0) ARRIVE_BOTH(hready, peer);   // initial h (zeros) ready

    for (int t = 0; t < TT; t++) {
        float acc[2][8][4];
        #pragma unroll
        for (int mt = 0; mt < 2; mt++)
            #pragma unroll
            for (int nt = 0; nt < 8; nt++)
                #pragma unroll
                for (int r = 0; r < 4; r++) acc[mt][nt][r] = 0.f;

        mbar_wait(hready, (uint32_t)(t & 1));

        #pragma unroll
        for (int kt = 0; kt < 16; kt++) {
            #pragma unroll
            for (int hn = 0; hn < 2; hn++) {
                uint32_t b0[4], b1[4];
                #pragma unroll
                for (int j = 0; j < 4; j++) {
                    int nt = hn * 4 + j;
                    asm volatile("ld.shared.v2.b32 {%0,%1}, [%2];"
                                 : "=r"(b0[j]), "=r"(b1[j])
                                 : "r"(hb_lane + kt * 2048 + nt * 256));
                }
                #pragma unroll
                for (int mt = 0; mt < 2; mt++)
                    #pragma unroll
                    for (int j = 0; j < 4; j++)
                        MMA_TF32(acc[mt][hn * 4 + j], wreg[mt][kt], b0[j], b1[j]);
            }
        }

        if (lane == 0) ARRIVE_BOTH(rdone, peer);    // this warp done reading h
        mbar_wait(rdone, (uint32_t)(t & 1));        // everyone done -> safe to overwrite

        #pragma unroll
        for (int nt = 0; nt < 8; nt++) {
            #pragma unroll
            for (int e = 0; e < 2; e++) {
                const int n = nt * 8 + tig * 2 + e;
                const float xv = xs[n * 129 + t];
                const float pi = acc[0][nt][e]     + fmaf(xv, wi[0], bsv[0]);
                const float pf = acc[0][nt][2 + e] + fmaf(xv, wi[1], bsv[1]);
                const float pg = acc[1][nt][e]     + fmaf(xv, wi[2], bsv[2]);
                const float po = acc[1][nt][2 + e] + fmaf(xv, wi[3], bsv[3]);
                const float gi = sig_ap(pi), gf = sig_ap(pf);
                const float gg = tanh_ap(pg), go = sig_ap(po);
                const float cn = fmaf(gf, cst[nt * 2 + e], gi * gg);
                cst[nt * 2 + e] = cn;
                const uint32_t hbits = rna_tf32(go * tanh_ap(cn));
                const uint32_t off = (uint32_t)(nt * 256 + tig * 64 + e * 32);
                asm volatile("st.shared.b32 [%0], %1;" :: "r"(hwL + off), "r"(hbits) : "memory");
                asm volatile("st.shared::cluster.b32 [%0], %1;" :: "r"(hwR + off), "r"(hbits) : "memory");
            }
        }
        if (lane == 0) ARRIVE_BOTH(hready, peer);   // new h published (both CTAs)
    }

    CLUSTER_SYNC();   // all final h writes (incl. peer remote stores) visible

    // ---- fc head: this CTA outputs batches crank*32 .. +31 of its cluster ----
    if (wid == 0) {
        const int n = (int)crank * 32 + lane;
        const float* hT = (const float*)(sm + OFF_H);
        float s = 0.f;
        #pragma unroll 8
        for (int k = 0; k < 128; k++) {
            const int idx = (k >> 3) * 512 + n * 8 + (k & 3) * 2 + ((k >> 2) & 1);
            s = fmaf(hT[idx], fc_W[k], s);
        }
        out[clid * 64 + n] = s + fc_b[0];
    }
    CLUSTER_SYNC();   // don't let a CTA exit while peer may still target its smem
}

extern "C" void kernel_launch(void* const* d_in, const int* in_sizes, int n_in,
                              void* d_out, int out_size)
{
    const float* x    = (const float*)d_in[0];
    const float* W_ih = (const float*)d_in[1];
    const float* W_hh = (const float*)d_in[2];
    const float* b_ih = (const float*)d_in[3];
    const float* b_hh = (const float*)d_in[4];
    const float* fc_W = (const float*)d_in[5];
    const float* fc_b = (const float*)d_in[6];

    const int B = in_sizes[0] / TT;        // 4096
    const int grid = (B / 64) * 2;         // 64 clusters x 2 CTAs = 128

    cudaFuncSetAttribute(lstm_mma, cudaFuncAttributeMaxDynamicSharedMemorySize, SMEM_REQ);
    lstm_mma<<<grid, NTHR, SMEM_REQ>>>(x, W_ih, W_hh, b_ih, b_hh, fc_W, fc_b, (float*)d_out);
}

// round 6
// speedup vs baseline: 20.1786x; 1.2407x over previous
#include <cuda_runtime.h>
#include <cuda_bf16.h>
#include <cstdint>

// LSTM_WP via mma.sync bf16 m16n8k16 (non-'a' PTX; sm_80+ baseline).
// Cluster of 2 CTAs; CTA rank c owns gate-rows for units c*64..c*64+63 (all
// 4 gates, M=256), W held in REGISTERS as bf16x2 frags (64 regs/thread).
// Per step: D[256,64] = W_c[256,128] @ h[128,64]; h in smem as bf16 pairs,
// layout word[kt][n][tig][khalf] = pack(h[kt*16+khalf*8+tig*2], h[..+1]) so
// B-frags are one conflict-free ld.shared.v2.b32.
// h double-buffered -> ONE cluster mbarrier per step (rdone is implied:
// hready arrivals happen after each warp's MMA of the previous step).
// Final-step h also stored fp32 for an exact fc head.

#define TT 128
#define NTHR 256
#define OFF_H   0                        // 2 x 16384 B bf16 h ping-pong
#define OFF_X   32768                    // 64 x 129 x 4 = 33024 B padded x
#define OFF_HF  65792                    // 64 x 129 x 4 fp32 final h
#define OFF_BAR 98816
#define SMEM_REQ (OFF_BAR + 32)

__device__ __forceinline__ uint32_t smem_u32(const void* p) {
    uint32_t a;
    asm("{ .reg .u64 t; cvta.to.shared.u64 t, %1; cvt.u32.u64 %0, t; }" : "=r"(a) : "l"(p));
    return a;
}
__device__ __forceinline__ uint32_t ctarank() {
    uint32_t r; asm("mov.u32 %0, %%cluster_ctarank;" : "=r"(r)); return r;
}
__device__ __forceinline__ uint32_t pk_bf16(float lo, float hi) {
    uint32_t r; asm("cvt.rn.bf16x2.f32 %0, %1, %2;" : "=r"(r) : "f"(hi), "f"(lo)); return r;
}
__device__ __forceinline__ float tanh_ap(float x) {
    float y; asm("tanh.approx.f32 %0, %1;" : "=f"(y) : "f"(x)); return y;
}
__device__ __forceinline__ float sig_ap(float x) { return fmaf(tanh_ap(0.5f * x), 0.5f, 0.5f); }

#define MBAR_INIT(a, n) \
    asm volatile("mbarrier.init.shared.b64 [%0], %1;" :: "r"(a), "r"((uint32_t)(n)) : "memory")

#define ARRIVE_BOTH(addr, peer) do { \
    asm volatile("mbarrier.arrive.release.cluster.shared::cta.b64 _, [%0];" \
                 :: "r"(addr) : "memory"); \
    asm volatile("{ .reg .b32 ra; mapa.shared::cluster.u32 ra, %0, %1;" \
                 " mbarrier.arrive.release.cluster.shared::cluster.b64 _, [ra]; }" \
                 :: "r"(addr), "r"((uint32_t)(peer)) : "memory"); \
} while (0)

__device__ __forceinline__ void mbar_wait(uint32_t a, uint32_t par) {
    uint32_t done;
    do {
        asm volatile("{ .reg .pred p;"
                     " mbarrier.try_wait.parity.acquire.cluster.shared::cta.b64 p, [%1], %2, 0x989680;"
                     " selp.b32 %0,1,0,p; }"
                     : "=r"(done) : "r"(a), "r"(par) : "memory");
    } while (!done);
}

#define CLUSTER_SYNC() do { \
    asm volatile("barrier.cluster.arrive.aligned;" ::: "memory"); \
    asm volatile("barrier.cluster.wait.aligned;"   ::: "memory"); } while (0)

#define MMA_BF16(d, a, b0, b1) \
    asm volatile("mma.sync.aligned.m16n8k16.row.col.f32.bf16.bf16.f32 " \
                 "{%0,%1,%2,%3}, {%4,%5,%6,%7}, {%8,%9}, {%0,%1,%2,%3};" \
                 : "+f"((d)[0]), "+f"((d)[1]), "+f"((d)[2]), "+f"((d)[3]) \
                 : "r"((a)[0]), "r"((a)[1]), "r"((a)[2]), "r"((a)[3]), \
                   "r"(b0), "r"(b1))

__global__ __launch_bounds__(NTHR, 1) __cluster_dims__(2, 1, 1)
void lstm_mma(const float* __restrict__ x,
              const float* __restrict__ W_ih,
              const float* __restrict__ W_hh,
              const float* __restrict__ b_ih,
              const float* __restrict__ b_hh,
              const float* __restrict__ fc_W,
              const float* __restrict__ fc_b,
              float* __restrict__ out)
{
    extern __shared__ char sm[];
    const uint32_t sbase = smem_u32(sm);
    const int tid  = threadIdx.x;
    const int wid  = tid >> 5, lane = tid & 31;
    const int gid  = lane >> 2, tig = lane & 3;
    const uint32_t crank = ctarank();
    const uint32_t peer  = crank ^ 1u;
    const int clid = blockIdx.x >> 1;

    const uint32_t hready0 = sbase + OFF_BAR;      // buffer-0 ready
    const uint32_t hready1 = sbase + OFF_BAR + 8;  // buffer-1 ready

    if (tid == 0) { MBAR_INIT(hready0, 16); MBAR_INIT(hready1, 16); }

    // zero h buffer 0 (16KB), load x into padded x_s[64][129]
    {
        float4 z = make_float4(0.f, 0.f, 0.f, 0.f);
        float4* hz = (float4*)(sm + OFF_H);
        #pragma unroll
        for (int i = tid; i < 1024; i += NTHR) hz[i] = z;
        const float4* xg = (const float4*)(x + (size_t)clid * 64 * TT);
        float* xs = (float*)(sm + OFF_X);
        #pragma unroll
        for (int i = tid; i < 2048; i += NTHR) {
            float4 v = xg[i];
            int n = i >> 5, q = (i & 31) * 4;
            float* d = xs + n * 129 + q;
            d[0] = v.x; d[1] = v.y; d[2] = v.z; d[3] = v.w;
        }
    }
    __syncthreads();
    CLUSTER_SYNC();   // peer mbars + smem ready

    // ---- W fragments in registers (bf16x2, 64 regs) ----
    const int u = (int)crank * 64 + wid * 8 + gid;   // hidden unit 0..127
    uint32_t wreg[2][8][4];
    #pragma unroll
    for (int mt = 0; mt < 2; mt++) {
        const float* rl = W_hh + (size_t)((2 * mt)     * 128 + u) * 128;
        const float* rh = W_hh + (size_t)((2 * mt + 1) * 128 + u) * 128;
        #pragma unroll
        for (int kt = 0; kt < 8; kt++) {
            int k0 = kt * 16 + tig * 2;
            wreg[mt][kt][0] = pk_bf16(__ldg(rl + k0),     __ldg(rl + k0 + 1));
            wreg[mt][kt][1] = pk_bf16(__ldg(rh + k0),     __ldg(rh + k0 + 1));
            wreg[mt][kt][2] = pk_bf16(__ldg(rl + k0 + 8), __ldg(rl + k0 + 9));
            wreg[mt][kt][3] = pk_bf16(__ldg(rh + k0 + 8), __ldg(rh + k0 + 9));
        }
    }
    float wi[4], bsv[4];
    #pragma unroll
    for (int g = 0; g < 4; g++) {
        int row = g * 128 + u;
        wi[g] = W_ih[row]; bsv[g] = b_ih[row] + b_hh[row];
    }

    uint32_t peerbase;
    asm("mapa.shared::cluster.u32 %0, %1, %2;" : "=r"(peerbase) : "r"(sbase), "r"(peer));

    // B-frag read base (per-thread), h write base (per unit-pair)
    const uint32_t bfrag = sbase + OFF_H + gid * 32 + tig * 8;
    const int upair = u & ~1;
    const uint32_t wordoff = (uint32_t)((upair >> 4) * 2048 + ((upair >> 1) & 3) * 8
                                        + ((upair >> 3) & 1) * 4);
    const bool even = ((gid & 1) == 0);
    const float* xs = (const float*)(sm + OFF_X);

    float cst[16];
    #pragma unroll
    for (int i = 0; i < 16; i++) cst[i] = 0.f;

    __syncwarp();
    if (lane == 0) ARRIVE_BOTH(hready0, peer);   // initial h (zeros) published

    for (int t = 0; t < TT; t++) {
        float acc[2][8][4];
        #pragma unroll
        for (int mt = 0; mt < 2; mt++)
            #pragma unroll
            for (int nt = 0; nt < 8; nt++)
                #pragma unroll
                for (int r = 0; r < 4; r++) acc[mt][nt][r] = 0.f;

        mbar_wait((t & 1) ? hready1 : hready0, (uint32_t)((t >> 1) & 1));

        const uint32_t rb = bfrag + (uint32_t)(t & 1) * 16384;
        #pragma unroll
        for (int kt = 0; kt < 8; kt++) {
            uint32_t b0[8], b1[8];
            #pragma unroll
            for (int nt = 0; nt < 8; nt++)
                asm volatile("ld.shared.v2.b32 {%0,%1}, [%2];"
                             : "=r"(b0[nt]), "=r"(b1[nt])
                             : "r"(rb + kt * 2048 + nt * 256));
            #pragma unroll
            for (int mt = 0; mt < 2; mt++)
                #pragma unroll
                for (int nt = 0; nt < 8; nt++)
                    MMA_BF16(acc[mt][nt], wreg[mt][kt], b0[nt], b1[nt]);
        }

        // epilogue -> write buffer (t+1)&1 (WAR-safe: hready wait above
        // implies all warps finished MMA of step t-1 on that buffer)
        const uint32_t wb   = (uint32_t)((t + 1) & 1) * 16384;
        const uint32_t wL   = sbase    + OFF_H + wb + wordoff;
        const uint32_t wR   = peerbase + OFF_H + wb + wordoff;
        #pragma unroll
        for (int nt = 0; nt < 8; nt++) {
            #pragma unroll
            for (int e = 0; e < 2; e++) {
                const int n = nt * 8 + tig * 2 + e;
                const float xv = xs[n * 129 + t];
                const float pi = acc[0][nt][e]     + fmaf(xv, wi[0], bsv[0]);
                const float pf = acc[0][nt][2 + e] + fmaf(xv, wi[1], bsv[1]);
                const float pg = acc[1][nt][e]     + fmaf(xv, wi[2], bsv[2]);
                const float po = acc[1][nt][2 + e] + fmaf(xv, wi[3], bsv[3]);
                const float gi = sig_ap(pi), gf = sig_ap(pf);
                const float gg = tanh_ap(pg), go = sig_ap(po);
                const float cn = fmaf(gf, cst[nt * 2 + e], gi * gg);
                cst[nt * 2 + e] = cn;
                const float hv = go * tanh_ap(cn);
                const float hp = __shfl_xor_sync(0xffffffffu, hv, 4);
                if (even) {
                    const uint32_t w = pk_bf16(hv, hp);
                    asm volatile("st.shared.b32 [%0], %1;"
                                 :: "r"(wL + (uint32_t)n * 32), "r"(w) : "memory");
                    asm volatile("st.shared::cluster.b32 [%0], %1;"
                                 :: "r"(wR + (uint32_t)n * 32), "r"(w) : "memory");
                    if (t == TT - 1) {   // exact fp32 h for the fc head
                        const uint32_t fo = (uint32_t)(OFF_HF + n * 516 + upair * 4);
                        asm volatile("st.shared.f32 [%0], %1;" :: "r"(sbase + fo), "f"(hv) : "memory");
                        asm volatile("st.shared.f32 [%0], %1;" :: "r"(sbase + fo + 4), "f"(hp) : "memory");
                        asm volatile("st.shared::cluster.f32 [%0], %1;" :: "r"(peerbase + fo), "f"(hv) : "memory");
                        asm volatile("st.shared::cluster.f32 [%0], %1;" :: "r"(peerbase + fo + 4), "f"(hp) : "memory");
                    }
                }
            }
        }
        __syncwarp();
        if (lane == 0) ARRIVE_BOTH((t & 1) ? hready0 : hready1, peer);
    }

    CLUSTER_SYNC();   // all final fp32 h writes (incl. peer stores) visible

    // ---- fc head on exact fp32 h ----
    if (wid == 0) {
        const int n = (int)crank * 32 + lane;
        const float* hf = (const float*)(sm + OFF_HF) + n * 129;
        float s = 0.f;
        #pragma unroll 8
        for (int k = 0; k < 128; k++) s = fmaf(hf[k], fc_W[k], s);
        out[clid * 64 + n] = s + fc_b[0];
    }
    CLUSTER_SYNC();
}

extern "C" void kernel_launch(void* const* d_in, const int* in_sizes, int n_in,
                              void* d_out, int out_size)
{
    const float* x    = (const float*)d_in[0];
    const float* W_ih = (const float*)d_in[1];
    const float* W_hh = (const float*)d_in[2];
    const float* b_ih = (const float*)d_in[3];
    const float* b_hh = (const float*)d_in[4];
    const float* fc_W = (const float*)d_in[5];
    const float* fc_b = (const float*)d_in[6];

    const int B = in_sizes[0] / TT;        // 4096
    const int grid = (B / 64) * 2;         // 64 clusters x 2 CTAs = 128

    cudaFuncSetAttribute(lstm_mma, cudaFuncAttributeMaxDynamicSharedMemorySize, SMEM_REQ);
    lstm_mma<<<grid, NTHR, SMEM_REQ>>>(x, W_ih, W_hh, b_ih, b_hh, fc_W, fc_b, (float*)d_out);
}